// round 1
// baseline (speedup 1.0000x reference)
#include <cuda_runtime.h>
#include <math.h>

// Problem constants (fixed shapes per reference setup_inputs)
constexpr int Bn   = 64;
constexpr int Hn   = 512;
constexpr int Wn   = 512;
constexpr int NPTS = 512;
constexpr int HWn  = Hn * Wn;
constexpr int SLICES = 16;          // reduce: blocks per image
constexpr float SCALE = 0.25f;      // 512/2048
constexpr double CELL_AREA = 16.0;

// Static scratch (zero-initialized module memory; restored to zero each call)
__device__ float  g_target[(size_t)Bn * HWn];   // 64 MB sparse target grid
__device__ double g_S[Bn];   // sum(pred)
__device__ double g_Q[Bn];   // sum(pred^2)
__device__ double g_T[Bn];   // sum of splat weights (tsum)
__device__ double g_A[Bn];   // sum_i w_i * pred[cell_i]
__device__ double g_C[Bn];   // sum_i w_i * t_raw[cell_i]

__device__ __forceinline__ float wgt_of(int r2) {
    // exp(-sqrt(r2)/2) for r2 in {0,1,2}, fp32-rounded
    return r2 == 0 ? 1.0f : (r2 == 1 ? 0.60653066f : 0.49306869f);
}

__global__ void k_init() {
    int i = threadIdx.x;
    if (i < Bn) { g_S[i] = 0.0; g_Q[i] = 0.0; g_T[i] = 0.0; g_A[i] = 0.0; g_C[i] = 0.0; }
}

// Per-image sum / sum-of-squares over pred. grid = (Bn, SLICES), 256 threads.
__global__ void k_reduce(const float* __restrict__ pred) {
    int b = blockIdx.x;
    int slice = blockIdx.y;
    constexpr int CH = HWn / 4 / SLICES;   // float4 per block = 4096
    const float4* p = reinterpret_cast<const float4*>(pred)
                      + (size_t)b * (HWn / 4) + (size_t)slice * CH;
    float s = 0.f, q = 0.f;
    for (int i = threadIdx.x; i < CH; i += blockDim.x) {
        float4 v = p[i];
        s += (v.x + v.y) + (v.z + v.w);
        q += v.x * v.x + v.y * v.y + v.z * v.z + v.w * v.w;
    }
    #pragma unroll
    for (int o = 16; o; o >>= 1) {
        s += __shfl_down_sync(0xffffffffu, s, o);
        q += __shfl_down_sync(0xffffffffu, q, o);
    }
    __shared__ float ss[8], sq[8];
    int lane = threadIdx.x & 31, wid = threadIdx.x >> 5;
    if (lane == 0) { ss[wid] = s; sq[wid] = q; }
    __syncthreads();
    if (wid == 0) {
        int nw = blockDim.x >> 5;
        s = (lane < nw) ? ss[lane] : 0.f;
        q = (lane < nw) ? sq[lane] : 0.f;
        #pragma unroll
        for (int o = 4; o; o >>= 1) {
            s += __shfl_down_sync(0xffffffffu, s, o);
            q += __shfl_down_sync(0xffffffffu, q, o);
        }
        if (lane == 0) {
            atomicAdd(&g_S[b], (double)s);
            atomicAdd(&g_Q[b], (double)q);
        }
    }
}

__device__ __forceinline__ void point_cell(const float* __restrict__ points,
                                           int t, int& b, int& x, int& y) {
    b = t / NPTS;
    float px = points[2 * t + 0];
    float py = points[2 * t + 1];
    x = (int)fminf(fmaxf(px * SCALE, 0.f), (float)(Wn - 1));
    y = (int)fminf(fmaxf(py * SCALE, 0.f), (float)(Hn - 1));
}

// Splat 3x3 gaussian weights into target grid; accumulate tsum per image.
__global__ void k_scatter(const float* __restrict__ points) {
    int t = blockIdx.x * blockDim.x + threadIdx.x;
    if (t >= Bn * NPTS) return;
    int b, x, y; point_cell(points, t, b, x, y);
    float* tg = g_target + (size_t)b * HWn;
    float wsum = 0.f;
    #pragma unroll
    for (int dy = -1; dy <= 1; ++dy)
        #pragma unroll
        for (int dx = -1; dx <= 1; ++dx) {
            int ny = y + dy, nx = x + dx;
            if ((unsigned)ny < (unsigned)Hn && (unsigned)nx < (unsigned)Wn) {
                float w = wgt_of(dy * dy + dx * dx);
                atomicAdd(&tg[ny * Wn + nx], w);
                wsum += w;
            }
        }
    // all lanes in a warp share b (NPTS % 32 == 0)
    #pragma unroll
    for (int o = 16; o; o >>= 1) wsum += __shfl_down_sync(0xffffffffu, wsum, o);
    if ((threadIdx.x & 31) == 0) atomicAdd(&g_T[b], (double)wsum);
}

// Gather cross terms: A = sum w*pred[cell], C = sum w*t_raw[cell].
__global__ void k_gather(const float* __restrict__ pred,
                         const float* __restrict__ points) {
    int t = blockIdx.x * blockDim.x + threadIdx.x;
    if (t >= Bn * NPTS) return;
    int b, x, y; point_cell(points, t, b, x, y);
    const float* pr = pred + (size_t)b * HWn;
    const float* tg = g_target + (size_t)b * HWn;
    float a = 0.f, c = 0.f;
    #pragma unroll
    for (int dy = -1; dy <= 1; ++dy)
        #pragma unroll
        for (int dx = -1; dx <= 1; ++dx) {
            int ny = y + dy, nx = x + dx;
            if ((unsigned)ny < (unsigned)Hn && (unsigned)nx < (unsigned)Wn) {
                float w = wgt_of(dy * dy + dx * dx);
                int idx = ny * Wn + nx;
                a += w * pr[idx];
                c += w * tg[idx];
            }
        }
    #pragma unroll
    for (int o = 16; o; o >>= 1) {
        a += __shfl_down_sync(0xffffffffu, a, o);
        c += __shfl_down_sync(0xffffffffu, c, o);
    }
    if ((threadIdx.x & 31) == 0) {
        atomicAdd(&g_A[b], (double)a);
        atomicAdd(&g_C[b], (double)c);
    }
}

// Restore target grid to zero (only touched cells) so the graph replays.
__global__ void k_clean(const float* __restrict__ points) {
    int t = blockIdx.x * blockDim.x + threadIdx.x;
    if (t >= Bn * NPTS) return;
    int b, x, y; point_cell(points, t, b, x, y);
    float* tg = g_target + (size_t)b * HWn;
    #pragma unroll
    for (int dy = -1; dy <= 1; ++dy)
        #pragma unroll
        for (int dx = -1; dx <= 1; ++dx) {
            int ny = y + dy, nx = x + dx;
            if ((unsigned)ny < (unsigned)Hn && (unsigned)nx < (unsigned)Wn)
                tg[ny * Wn + nx] = 0.f;
        }
}

__global__ void k_final(float* __restrict__ out) {
    int b = threadIdx.x;   // 64 threads
    double cnt = 0.0, sp = 0.0;
    if (b < Bn) {
        double S = g_S[b];
        cnt = fabs(S / CELL_AREA - (double)NPTS);
        double Sp = S + 1e-8;
        double T = g_T[b];
        sp = (g_Q[b] / (Sp * Sp) - 2.0 * g_A[b] / (Sp * T) + g_C[b] / (T * T))
             / (double)HWn;
    }
    #pragma unroll
    for (int o = 16; o; o >>= 1) {
        cnt += __shfl_down_sync(0xffffffffu, cnt, o);
        sp  += __shfl_down_sync(0xffffffffu, sp, o);
    }
    __shared__ double sc[2], ssp[2];
    int lane = threadIdx.x & 31, wid = threadIdx.x >> 5;
    if (lane == 0) { sc[wid] = cnt; ssp[wid] = sp; }
    __syncthreads();
    if (threadIdx.x == 0) {
        double count_loss = (sc[0] + sc[1]) / (double)Bn;
        double spatial    = (ssp[0] + ssp[1]) / (double)Bn;
        out[0] = (float)(2.5 * count_loss + 0.1 * spatial);
        out[1] = (float)count_loss;
        out[2] = (float)spatial;
    }
}

extern "C" void kernel_launch(void* const* d_in, const int* in_sizes, int n_in,
                              void* d_out, int out_size) {
    const float* pred   = (const float*)d_in[0];
    const float* points = (const float*)d_in[1];
    float* out = (float*)d_out;

    constexpr int NT = Bn * NPTS;
    k_init<<<1, 64>>>();
    k_reduce<<<dim3(Bn, SLICES), 256>>>(pred);
    k_scatter<<<(NT + 255) / 256, 256>>>(points);
    k_gather<<<(NT + 255) / 256, 256>>>(pred, points);
    k_clean<<<(NT + 255) / 256, 256>>>(points);
    k_final<<<1, 64>>>(out);
}